// round 11
// baseline (speedup 1.0000x reference)
#include <cuda_runtime.h>

#define DEV_INLINE __device__ __forceinline__

// Problem constants
constexpr int Bb   = 2;
constexpr int Ss   = 2048;
constexpr int DIMd = 1024;
constexpr int Hh   = 16;
constexpr int Ww   = 256;
constexpr int HDd  = 64;
constexpr float SCALEc = 0.125f;  // 1/sqrt(64)

constexpr int GM = Bb * Ss;  // 4096
constexpr int GN = DIMd;     // 1024
constexpr int GK = DIMd;     // 1024

// Scratch (device globals — no allocations allowed)
__device__ float g_q[GM * DIMd];
__device__ float g_k[GM * DIMd];
__device__ float g_v[GM * DIMd];
__device__ float g_c[GM * DIMd];

// ---------------- packed fp32x2 helpers (Blackwell) ----------------
DEV_INLINE unsigned long long dup2(float x) {
    unsigned long long r;
    asm("mov.b64 %0, {%1,%1};" : "=l"(r) : "f"(x));
    return r;
}
DEV_INLINE float2 unp2(unsigned long long v) {
    float2 r;
    asm("mov.b64 {%0,%1}, %2;" : "=f"(r.x), "=f"(r.y) : "l"(v));
    return r;
}
DEV_INLINE void ffma2(unsigned long long& d, unsigned long long a, unsigned long long b) {
    asm("fma.rn.f32x2 %0, %1, %2, %0;" : "+l"(d) : "l"(a), "l"(b));
}
DEV_INLINE unsigned long long mul2(unsigned long long a, unsigned long long b) {
    unsigned long long d;
    asm("mul.rn.f32x2 %0, %1, %2;" : "=l"(d) : "l"(a), "l"(b));
    return d;
}

// ---------------- SGEMM: C[4096,1024] = A @ W + bias ----------------
// BM=128, BN=128, BK=16, 256 threads, 8x8 micro-tile, f32x2 packed FMA.
DEV_INLINE void sgemm_body(const float* __restrict__ A, const float* __restrict__ Wm,
                           const float* __restrict__ bias, float* __restrict__ C) {
    __shared__ float As[16 * 132];  // transposed A tile: As[k][m]
    __shared__ float Bs[16 * 132];  // Bs[k][n]

    const int tid = threadIdx.x;
    const int tx = tid & 15;   // 0..15 -> n micro-tile
    const int ty = tid >> 4;   // 0..15 -> m micro-tile
    const int m0 = blockIdx.y << 7;
    const int n0 = blockIdx.x << 7;

    const int ar = tid >> 2;          // 0..63 (A row within tile; +64 for second)
    const int ac = (tid & 3) << 2;    // 0,4,8,12 (k offset)
    const int br = tid >> 4;          // 0..15 (B row = k)
    const int bc = (tid & 15) << 3;   // 0..120 (n offset)

    unsigned long long acc[8][4];
#pragma unroll
    for (int i = 0; i < 8; i++) {
        acc[i][0] = 0ull; acc[i][1] = 0ull; acc[i][2] = 0ull; acc[i][3] = 0ull;
    }

    const float* Aptr0 = A + (long)(m0 + ar) * GK + ac;
    const float* Aptr1 = A + (long)(m0 + ar + 64) * GK + ac;
    const float* Bptr  = Wm + (long)br * GN + n0 + bc;

    for (int kb = 0; kb < GK; kb += 16) {
        const float4 a0 = *reinterpret_cast<const float4*>(Aptr0 + kb);
        const float4 a1 = *reinterpret_cast<const float4*>(Aptr1 + kb);
        const float4 b0 = *reinterpret_cast<const float4*>(Bptr + (long)kb * GN);
        const float4 b1 = *reinterpret_cast<const float4*>(Bptr + (long)kb * GN + 4);
        __syncthreads();
        As[(ac + 0) * 132 + ar] = a0.x;
        As[(ac + 1) * 132 + ar] = a0.y;
        As[(ac + 2) * 132 + ar] = a0.z;
        As[(ac + 3) * 132 + ar] = a0.w;
        As[(ac + 0) * 132 + ar + 64] = a1.x;
        As[(ac + 1) * 132 + ar + 64] = a1.y;
        As[(ac + 2) * 132 + ar + 64] = a1.z;
        As[(ac + 3) * 132 + ar + 64] = a1.w;
        *reinterpret_cast<float4*>(&Bs[br * 132 + bc]) = b0;
        *reinterpret_cast<float4*>(&Bs[br * 132 + bc + 4]) = b1;
        __syncthreads();

#pragma unroll
        for (int k = 0; k < 16; k++) {
            const float4 af0 = *reinterpret_cast<const float4*>(&As[k * 132 + ty * 8]);
            const float4 af1 = *reinterpret_cast<const float4*>(&As[k * 132 + ty * 8 + 4]);
            const ulonglong2 bq0 = *reinterpret_cast<const ulonglong2*>(&Bs[k * 132 + tx * 8]);
            const ulonglong2 bq1 = *reinterpret_cast<const ulonglong2*>(&Bs[k * 132 + tx * 8 + 4]);
            const float a[8] = {af0.x, af0.y, af0.z, af0.w, af1.x, af1.y, af1.z, af1.w};
            const unsigned long long bpk[4] = {bq0.x, bq0.y, bq1.x, bq1.y};
#pragma unroll
            for (int i = 0; i < 8; i++) {
                const unsigned long long ad = dup2(a[i]);
                ffma2(acc[i][0], ad, bpk[0]);
                ffma2(acc[i][1], ad, bpk[1]);
                ffma2(acc[i][2], ad, bpk[2]);
                ffma2(acc[i][3], ad, bpk[3]);
            }
        }
    }

    const float4 bb0 = *reinterpret_cast<const float4*>(&bias[n0 + tx * 8]);
    const float4 bb1 = *reinterpret_cast<const float4*>(&bias[n0 + tx * 8 + 4]);
#pragma unroll
    for (int i = 0; i < 8; i++) {
        const float2 c0 = unp2(acc[i][0]);
        const float2 c1 = unp2(acc[i][1]);
        const float2 c2 = unp2(acc[i][2]);
        const float2 c3 = unp2(acc[i][3]);
        float4 r0, r1;
        r0.x = c0.x + bb0.x; r0.y = c0.y + bb0.y; r0.z = c1.x + bb0.z; r0.w = c1.y + bb0.w;
        r1.x = c2.x + bb1.x; r1.y = c2.y + bb1.y; r1.z = c3.x + bb1.z; r1.w = c3.y + bb1.w;
        float* cp = C + (long)(m0 + ty * 8 + i) * GN + n0 + tx * 8;
        *reinterpret_cast<float4*>(cp)     = r0;
        *reinterpret_cast<float4*>(cp + 4) = r1;
    }
}

__global__ __launch_bounds__(256, 2)
void k_qkv(const float* __restrict__ X,
           const float* __restrict__ Wq, const float* __restrict__ bq,
           const float* __restrict__ Wk, const float* __restrict__ bk,
           const float* __restrict__ Wv, const float* __restrict__ bv) {
    const float* Wm;
    const float* bias;
    float* C;
    if (blockIdx.z == 0)      { Wm = Wq; bias = bq; C = g_q; }
    else if (blockIdx.z == 1) { Wm = Wk; bias = bk; C = g_k; }
    else                      { Wm = Wv; bias = bv; C = g_v; }
    sgemm_body(X, Wm, bias, C);
}

__global__ __launch_bounds__(256, 2)
void k_out(const float* __restrict__ Wo, const float* __restrict__ bo,
           float* __restrict__ out) {
    sgemm_body(g_c, Wo, bo, out);
}

// ---------------- Sliding-window flash attention ----------------
// 1 CTA = (b, h, 128 queries). Key tiles of 128. smem:
//   Qt [64][132]  (transposed, pre-scaled)
//   KP [128][132] (Kt [64][132] during S-GEMM, then Pt [128 keys][128 q] swizzled)
//   Vs [128][68]
constexpr int ATTN_SMEM_FLOATS = 64 * 132 + 128 * 132 + 128 * 68;
constexpr int ATTN_SMEM_BYTES  = ATTN_SMEM_FLOATS * 4;  // 136192

// P swizzle: rotate q-column by 4*(k>>3) to break STS bank conflicts; shift is a
// multiple of 4 so float4 groups stay contiguous.
DEV_INLINE int p_col(int k, int q) { return (q + ((k >> 3) << 2)) & 127; }

__global__ __launch_bounds__(256, 1)
void k_attn() {
    extern __shared__ float sm[];
    float* Qt = sm;                        // 64*132
    float* KP = sm + 64 * 132;             // 128*132
    float* Vs = sm + 64 * 132 + 128 * 132; // 128*68

    const int tid = threadIdx.x;
    const int tx = tid & 15;
    const int ty = tid >> 4;
    const int q0 = blockIdx.x << 7;
    const int h  = blockIdx.y;
    const int b  = blockIdx.z;
    const long base = (long)b * Ss * DIMd + h * HDd;

    // Load Q tile (transposed + pre-scaled)
    {
        const int qq = tid >> 1;           // 0..127
        const int dh = (tid & 1) << 5;     // 0 or 32
        const float* src = g_q + base + (long)(q0 + qq) * DIMd + dh;
#pragma unroll
        for (int u = 0; u < 8; u++) {
            const float4 v = *reinterpret_cast<const float4*>(src + u * 4);
            const int d = dh + u * 4;
            Qt[(d + 0) * 132 + qq] = v.x * SCALEc;
            Qt[(d + 1) * 132 + qq] = v.y * SCALEc;
            Qt[(d + 2) * 132 + qq] = v.z * SCALEc;
            Qt[(d + 3) * 132 + qq] = v.w * SCALEc;
        }
    }

    float mrow[8], lrow[8];
    unsigned long long o2[8][2];
#pragma unroll
    for (int i = 0; i < 8; i++) {
        mrow[i] = -1e30f;
        lrow[i] = 0.f;
        o2[i][0] = 0ull;
        o2[i][1] = 0ull;
    }

    int kstart = q0 - (Ww - 1);
    if (kstart < 0) kstart = 0;
    const int kt_lo = kstart >> 7;
    const int kt_hi = q0 >> 7;

    for (int kt = kt_lo; kt <= kt_hi; kt++) {
        const int kbase = kt << 7;
        __syncthreads();  // previous-tile Pt/Vs consumers done
        {
            const int kk = tid >> 1;
            const int dh = (tid & 1) << 5;
            const float* ksrc = g_k + base + (long)(kbase + kk) * DIMd + dh;
            const float* vsrc = g_v + base + (long)(kbase + kk) * DIMd + dh;
#pragma unroll
            for (int u = 0; u < 8; u++) {
                const int d = dh + u * 4;
                const float4 kv = *reinterpret_cast<const float4*>(ksrc + u * 4);
                KP[(d + 0) * 132 + kk] = kv.x;
                KP[(d + 1) * 132 + kk] = kv.y;
                KP[(d + 2) * 132 + kk] = kv.z;
                KP[(d + 3) * 132 + kk] = kv.w;
                *reinterpret_cast<float4*>(&Vs[kk * 68 + d]) =
                    *reinterpret_cast<const float4*>(vsrc + u * 4);
            }
        }
        __syncthreads();

        // S = Q K^T (128x128), 8x8 per thread, packed
        unsigned long long s2[8][4];
#pragma unroll
        for (int i = 0; i < 8; i++) {
            s2[i][0] = 0ull; s2[i][1] = 0ull; s2[i][2] = 0ull; s2[i][3] = 0ull;
        }
#pragma unroll 4
        for (int d = 0; d < 64; d++) {
            const float4 qf0 = *reinterpret_cast<const float4*>(&Qt[d * 132 + ty * 8]);
            const float4 qf1 = *reinterpret_cast<const float4*>(&Qt[d * 132 + ty * 8 + 4]);
            const ulonglong2 kf0 = *reinterpret_cast<const ulonglong2*>(&KP[d * 132 + tx * 8]);
            const ulonglong2 kf1 = *reinterpret_cast<const ulonglong2*>(&KP[d * 132 + tx * 8 + 4]);
            const float qa[8] = {qf0.x, qf0.y, qf0.z, qf0.w, qf1.x, qf1.y, qf1.z, qf1.w};
            const unsigned long long kpk[4] = {kf0.x, kf0.y, kf1.x, kf1.y};
#pragma unroll
            for (int i = 0; i < 8; i++) {
                const unsigned long long qd = dup2(qa[i]);
                ffma2(s2[i][0], qd, kpk[0]);
                ffma2(s2[i][1], qd, kpk[1]);
                ffma2(s2[i][2], qd, kpk[2]);
                ffma2(s2[i][3], qd, kpk[3]);
            }
        }
        __syncthreads();  // all Kt reads complete before Pt overwrite

        // Masked online softmax; write P (transposed, swizzled) into KP
#pragma unroll
        for (int i = 0; i < 8; i++) {
            const int qi = q0 + ty * 8 + i;
            float sv[8];
            const float2 t0 = unp2(s2[i][0]); sv[0] = t0.x; sv[1] = t0.y;
            const float2 t1 = unp2(s2[i][1]); sv[2] = t1.x; sv[3] = t1.y;
            const float2 t2 = unp2(s2[i][2]); sv[4] = t2.x; sv[5] = t2.y;
            const float2 t3 = unp2(s2[i][3]); sv[6] = t3.x; sv[7] = t3.y;
            const int kcol = kbase + tx * 8;
#pragma unroll
            for (int j = 0; j < 8; j++) {
                const int kj = kcol + j;
                if (kj > qi || kj < qi - (Ww - 1)) sv[j] = -1e30f;
            }
            float mx = sv[0];
#pragma unroll
            for (int j = 1; j < 8; j++) mx = fmaxf(mx, sv[j]);
#pragma unroll
            for (int off = 1; off < 16; off <<= 1)
                mx = fmaxf(mx, __shfl_xor_sync(0xFFFFFFFFu, mx, off));
            const float mnew = fmaxf(mrow[i], mx);
            const float corr = __expf(mrow[i] - mnew);
            mrow[i] = mnew;
            float rs = 0.f;
#pragma unroll
            for (int j = 0; j < 8; j++) {
                sv[j] = __expf(sv[j] - mnew);
                rs += sv[j];
            }
#pragma unroll
            for (int off = 1; off < 16; off <<= 1)
                rs += __shfl_xor_sync(0xFFFFFFFFu, rs, off);
            lrow[i] = lrow[i] * corr + rs;
            const unsigned long long cd = dup2(corr);
            o2[i][0] = mul2(o2[i][0], cd);
            o2[i][1] = mul2(o2[i][1], cd);
#pragma unroll
            for (int j = 0; j < 8; j++) {
                const int kq = tx * 8 + j;
                KP[kq * 132 + p_col(kq, ty * 8 + i)] = sv[j];
            }
        }
        __syncthreads();

        // O += P V  (128x64), thread owns q = ty*8..+7, d = tx*4..+3
#pragma unroll 4
        for (int k = 0; k < 128; k++) {
            const int sh = (k >> 3) << 2;
            const int qo0 = (ty * 8 + sh) & 127;
            const int qo1 = (ty * 8 + 4 + sh) & 127;
            const float4 pf0 = *reinterpret_cast<const float4*>(&KP[k * 132 + qo0]);
            const float4 pf1 = *reinterpret_cast<const float4*>(&KP[k * 132 + qo1]);
            const ulonglong2 vv = *reinterpret_cast<const ulonglong2*>(&Vs[k * 68 + tx * 4]);
            const float pa[8] = {pf0.x, pf0.y, pf0.z, pf0.w, pf1.x, pf1.y, pf1.z, pf1.w};
#pragma unroll
            for (int i = 0; i < 8; i++) {
                const unsigned long long pd = dup2(pa[i]);
                ffma2(o2[i][0], pd, vv.x);
                ffma2(o2[i][1], pd, vv.y);
            }
        }
    }

    // Normalize and write context in [B,S,H,HD] (== [B,S,DIM]) layout
#pragma unroll
    for (int i = 0; i < 8; i++) {
        const float inv = 1.0f / lrow[i];
        const float2 a0 = unp2(o2[i][0]);
        const float2 a1 = unp2(o2[i][1]);
        float4 r;
        r.x = a0.x * inv; r.y = a0.y * inv; r.z = a1.x * inv; r.w = a1.y * inv;
        *reinterpret_cast<float4*>(&g_c[base + (long)(q0 + ty * 8 + i) * DIMd + tx * 4]) = r;
    }
}

// ---------------- launch ----------------
extern "C" void kernel_launch(void* const* d_in, const int* in_sizes, int n_in,
                              void* d_out, int out_size) {
    const float* x  = (const float*)d_in[0];
    const float* Wq = (const float*)d_in[1];
    const float* bq = (const float*)d_in[2];
    const float* Wk = (const float*)d_in[3];
    const float* bk = (const float*)d_in[4];
    const float* Wv = (const float*)d_in[5];
    const float* bv = (const float*)d_in[6];
    const float* Wo = (const float*)d_in[7];
    const float* bo = (const float*)d_in[8];
    float* out = (float*)d_out;

    cudaFuncSetAttribute(k_attn, cudaFuncAttributeMaxDynamicSharedMemorySize, ATTN_SMEM_BYTES);

    k_qkv<<<dim3(GN / 128, GM / 128, 3), 256>>>(x, Wq, bq, Wk, bk, Wv, bv);
    k_attn<<<dim3(Ss / 128, Hh, Bb), 256, ATTN_SMEM_BYTES>>>();
    k_out<<<dim3(GN / 128, GM / 128, 1), 256>>>(Wo, bo, out);
}

// round 14
// speedup vs baseline: 1.0006x; 1.0006x over previous
#include <cuda_runtime.h>

#define DEV_INLINE __device__ __forceinline__

// Problem constants
constexpr int Bb   = 2;
constexpr int Ss   = 2048;
constexpr int DIMd = 1024;
constexpr int Hh   = 16;
constexpr int Ww   = 256;
constexpr int HDd  = 64;
constexpr float SCALEc = 0.125f;  // 1/sqrt(64)

constexpr int GM = Bb * Ss;  // 4096
constexpr int GN = DIMd;     // 1024
constexpr int GK = DIMd;     // 1024

// Scratch (device globals — no allocations allowed)
__device__ float g_q[GM * DIMd];
__device__ float g_k[GM * DIMd];
__device__ float g_v[GM * DIMd];
__device__ float g_c[GM * DIMd];

// ---------------- packed fp32x2 helpers (Blackwell) ----------------
DEV_INLINE unsigned long long dup2(float x) {
    unsigned long long r;
    asm("mov.b64 %0, {%1,%1};" : "=l"(r) : "f"(x));
    return r;
}
DEV_INLINE float2 unp2(unsigned long long v) {
    float2 r;
    asm("mov.b64 {%0,%1}, %2;" : "=f"(r.x), "=f"(r.y) : "l"(v));
    return r;
}
DEV_INLINE void ffma2(unsigned long long& d, unsigned long long a, unsigned long long b) {
    asm("fma.rn.f32x2 %0, %1, %2, %0;" : "+l"(d) : "l"(a), "l"(b));
}
DEV_INLINE unsigned long long mul2(unsigned long long a, unsigned long long b) {
    unsigned long long d;
    asm("mul.rn.f32x2 %0, %1, %2;" : "=l"(d) : "l"(a), "l"(b));
    return d;
}

// ---------------- SGEMM: C[4096,1024] = A @ W + bias ----------------
// BM=128, BN=128, BK=16, 256 threads, 8x8 micro-tile, f32x2 packed FMA.
DEV_INLINE void sgemm_body(const float* __restrict__ A, const float* __restrict__ Wm,
                           const float* __restrict__ bias, float* __restrict__ C) {
    __shared__ float As[16 * 132];  // transposed A tile: As[k][m]
    __shared__ float Bs[16 * 132];  // Bs[k][n]

    const int tid = threadIdx.x;
    const int tx = tid & 15;   // 0..15 -> n micro-tile
    const int ty = tid >> 4;   // 0..15 -> m micro-tile
    const int m0 = blockIdx.y << 7;
    const int n0 = blockIdx.x << 7;

    const int ar = tid >> 2;          // 0..63 (A row within tile; +64 for second)
    const int ac = (tid & 3) << 2;    // 0,4,8,12 (k offset)
    const int br = tid >> 4;          // 0..15 (B row = k)
    const int bc = (tid & 15) << 3;   // 0..120 (n offset)

    unsigned long long acc[8][4];
#pragma unroll
    for (int i = 0; i < 8; i++) {
        acc[i][0] = 0ull; acc[i][1] = 0ull; acc[i][2] = 0ull; acc[i][3] = 0ull;
    }

    const float* Aptr0 = A + (long)(m0 + ar) * GK + ac;
    const float* Aptr1 = A + (long)(m0 + ar + 64) * GK + ac;
    const float* Bptr  = Wm + (long)br * GN + n0 + bc;

    for (int kb = 0; kb < GK; kb += 16) {
        const float4 a0 = *reinterpret_cast<const float4*>(Aptr0 + kb);
        const float4 a1 = *reinterpret_cast<const float4*>(Aptr1 + kb);
        const float4 b0 = *reinterpret_cast<const float4*>(Bptr + (long)kb * GN);
        const float4 b1 = *reinterpret_cast<const float4*>(Bptr + (long)kb * GN + 4);
        __syncthreads();
        As[(ac + 0) * 132 + ar] = a0.x;
        As[(ac + 1) * 132 + ar] = a0.y;
        As[(ac + 2) * 132 + ar] = a0.z;
        As[(ac + 3) * 132 + ar] = a0.w;
        As[(ac + 0) * 132 + ar + 64] = a1.x;
        As[(ac + 1) * 132 + ar + 64] = a1.y;
        As[(ac + 2) * 132 + ar + 64] = a1.z;
        As[(ac + 3) * 132 + ar + 64] = a1.w;
        *reinterpret_cast<float4*>(&Bs[br * 132 + bc]) = b0;
        *reinterpret_cast<float4*>(&Bs[br * 132 + bc + 4]) = b1;
        __syncthreads();

#pragma unroll
        for (int k = 0; k < 16; k++) {
            const float4 af0 = *reinterpret_cast<const float4*>(&As[k * 132 + ty * 8]);
            const float4 af1 = *reinterpret_cast<const float4*>(&As[k * 132 + ty * 8 + 4]);
            const ulonglong2 bq0 = *reinterpret_cast<const ulonglong2*>(&Bs[k * 132 + tx * 8]);
            const ulonglong2 bq1 = *reinterpret_cast<const ulonglong2*>(&Bs[k * 132 + tx * 8 + 4]);
            const float a[8] = {af0.x, af0.y, af0.z, af0.w, af1.x, af1.y, af1.z, af1.w};
            const unsigned long long bpk[4] = {bq0.x, bq0.y, bq1.x, bq1.y};
#pragma unroll
            for (int i = 0; i < 8; i++) {
                const unsigned long long ad = dup2(a[i]);
                ffma2(acc[i][0], ad, bpk[0]);
                ffma2(acc[i][1], ad, bpk[1]);
                ffma2(acc[i][2], ad, bpk[2]);
                ffma2(acc[i][3], ad, bpk[3]);
            }
        }
    }

    const float4 bb0 = *reinterpret_cast<const float4*>(&bias[n0 + tx * 8]);
    const float4 bb1 = *reinterpret_cast<const float4*>(&bias[n0 + tx * 8 + 4]);
#pragma unroll
    for (int i = 0; i < 8; i++) {
        const float2 c0 = unp2(acc[i][0]);
        const float2 c1 = unp2(acc[i][1]);
        const float2 c2 = unp2(acc[i][2]);
        const float2 c3 = unp2(acc[i][3]);
        float4 r0, r1;
        r0.x = c0.x + bb0.x; r0.y = c0.y + bb0.y; r0.z = c1.x + bb0.z; r0.w = c1.y + bb0.w;
        r1.x = c2.x + bb1.x; r1.y = c2.y + bb1.y; r1.z = c3.x + bb1.z; r1.w = c3.y + bb1.w;
        float* cp = C + (long)(m0 + ty * 8 + i) * GN + n0 + tx * 8;
        *reinterpret_cast<float4*>(cp)     = r0;
        *reinterpret_cast<float4*>(cp + 4) = r1;
    }
}

__global__ __launch_bounds__(256, 2)
void k_qkv(const float* __restrict__ X,
           const float* __restrict__ Wq, const float* __restrict__ bq,
           const float* __restrict__ Wk, const float* __restrict__ bk,
           const float* __restrict__ Wv, const float* __restrict__ bv) {
    const float* Wm;
    const float* bias;
    float* C;
    if (blockIdx.z == 0)      { Wm = Wq; bias = bq; C = g_q; }
    else if (blockIdx.z == 1) { Wm = Wk; bias = bk; C = g_k; }
    else                      { Wm = Wv; bias = bv; C = g_v; }
    sgemm_body(X, Wm, bias, C);
}

__global__ __launch_bounds__(256, 2)
void k_out(const float* __restrict__ Wo, const float* __restrict__ bo,
           float* __restrict__ out) {
    sgemm_body(g_c, Wo, bo, out);
}

// ---------------- Sliding-window flash attention ----------------
// 1 CTA = (b, h, 128 queries). Key tiles of 128. smem:
//   Qt [64][132]  (transposed, pre-scaled)
//   KP [128][132] (Kt [64][132] during S-GEMM, then Pt [128 keys][128 q] swizzled)
//   Vs [128][68]
constexpr int ATTN_SMEM_FLOATS = 64 * 132 + 128 * 132 + 128 * 68;
constexpr int ATTN_SMEM_BYTES  = ATTN_SMEM_FLOATS * 4;  // 136192

// P swizzle: rotate q-column by 4*(k>>3) to break STS bank conflicts; shift is a
// multiple of 4 so float4 groups stay contiguous.
DEV_INLINE int p_col(int k, int q) { return (q + ((k >> 3) << 2)) & 127; }

__global__ __launch_bounds__(256, 1)
void k_attn() {
    extern __shared__ float sm[];
    float* Qt = sm;                        // 64*132
    float* KP = sm + 64 * 132;             // 128*132
    float* Vs = sm + 64 * 132 + 128 * 132; // 128*68

    const int tid = threadIdx.x;
    const int tx = tid & 15;
    const int ty = tid >> 4;
    const int q0 = blockIdx.x << 7;
    const int h  = blockIdx.y;
    const int b  = blockIdx.z;
    const long base = (long)b * Ss * DIMd + h * HDd;

    // Load Q tile (transposed + pre-scaled)
    {
        const int qq = tid >> 1;           // 0..127
        const int dh = (tid & 1) << 5;     // 0 or 32
        const float* src = g_q + base + (long)(q0 + qq) * DIMd + dh;
#pragma unroll
        for (int u = 0; u < 8; u++) {
            const float4 v = *reinterpret_cast<const float4*>(src + u * 4);
            const int d = dh + u * 4;
            Qt[(d + 0) * 132 + qq] = v.x * SCALEc;
            Qt[(d + 1) * 132 + qq] = v.y * SCALEc;
            Qt[(d + 2) * 132 + qq] = v.z * SCALEc;
            Qt[(d + 3) * 132 + qq] = v.w * SCALEc;
        }
    }

    float mrow[8], lrow[8];
    unsigned long long o2[8][2];
#pragma unroll
    for (int i = 0; i < 8; i++) {
        mrow[i] = -1e30f;
        lrow[i] = 0.f;
        o2[i][0] = 0ull;
        o2[i][1] = 0ull;
    }

    int kstart = q0 - (Ww - 1);
    if (kstart < 0) kstart = 0;
    const int kt_lo = kstart >> 7;
    const int kt_hi = q0 >> 7;

    for (int kt = kt_lo; kt <= kt_hi; kt++) {
        const int kbase = kt << 7;
        __syncthreads();  // previous-tile Pt/Vs consumers done
        {
            const int kk = tid >> 1;
            const int dh = (tid & 1) << 5;
            const float* ksrc = g_k + base + (long)(kbase + kk) * DIMd + dh;
            const float* vsrc = g_v + base + (long)(kbase + kk) * DIMd + dh;
#pragma unroll
            for (int u = 0; u < 8; u++) {
                const int d = dh + u * 4;
                const float4 kv = *reinterpret_cast<const float4*>(ksrc + u * 4);
                KP[(d + 0) * 132 + kk] = kv.x;
                KP[(d + 1) * 132 + kk] = kv.y;
                KP[(d + 2) * 132 + kk] = kv.z;
                KP[(d + 3) * 132 + kk] = kv.w;
                *reinterpret_cast<float4*>(&Vs[kk * 68 + d]) =
                    *reinterpret_cast<const float4*>(vsrc + u * 4);
            }
        }
        __syncthreads();

        // S = Q K^T (128x128), 8x8 per thread, packed
        unsigned long long s2[8][4];
#pragma unroll
        for (int i = 0; i < 8; i++) {
            s2[i][0] = 0ull; s2[i][1] = 0ull; s2[i][2] = 0ull; s2[i][3] = 0ull;
        }
#pragma unroll 4
        for (int d = 0; d < 64; d++) {
            const float4 qf0 = *reinterpret_cast<const float4*>(&Qt[d * 132 + ty * 8]);
            const float4 qf1 = *reinterpret_cast<const float4*>(&Qt[d * 132 + ty * 8 + 4]);
            const ulonglong2 kf0 = *reinterpret_cast<const ulonglong2*>(&KP[d * 132 + tx * 8]);
            const ulonglong2 kf1 = *reinterpret_cast<const ulonglong2*>(&KP[d * 132 + tx * 8 + 4]);
            const float qa[8] = {qf0.x, qf0.y, qf0.z, qf0.w, qf1.x, qf1.y, qf1.z, qf1.w};
            const unsigned long long kpk[4] = {kf0.x, kf0.y, kf1.x, kf1.y};
#pragma unroll
            for (int i = 0; i < 8; i++) {
                const unsigned long long qd = dup2(qa[i]);
                ffma2(s2[i][0], qd, kpk[0]);
                ffma2(s2[i][1], qd, kpk[1]);
                ffma2(s2[i][2], qd, kpk[2]);
                ffma2(s2[i][3], qd, kpk[3]);
            }
        }
        __syncthreads();  // all Kt reads complete before Pt overwrite

        // Masked online softmax; write P (transposed, swizzled) into KP
#pragma unroll
        for (int i = 0; i < 8; i++) {
            const int qi = q0 + ty * 8 + i;
            float sv[8];
            const float2 t0 = unp2(s2[i][0]); sv[0] = t0.x; sv[1] = t0.y;
            const float2 t1 = unp2(s2[i][1]); sv[2] = t1.x; sv[3] = t1.y;
            const float2 t2 = unp2(s2[i][2]); sv[4] = t2.x; sv[5] = t2.y;
            const float2 t3 = unp2(s2[i][3]); sv[6] = t3.x; sv[7] = t3.y;
            const int kcol = kbase + tx * 8;
#pragma unroll
            for (int j = 0; j < 8; j++) {
                const int kj = kcol + j;
                if (kj > qi || kj < qi - (Ww - 1)) sv[j] = -1e30f;
            }
            float mx = sv[0];
#pragma unroll
            for (int j = 1; j < 8; j++) mx = fmaxf(mx, sv[j]);
#pragma unroll
            for (int off = 1; off < 16; off <<= 1)
                mx = fmaxf(mx, __shfl_xor_sync(0xFFFFFFFFu, mx, off));
            const float mnew = fmaxf(mrow[i], mx);
            const float corr = __expf(mrow[i] - mnew);
            mrow[i] = mnew;
            float rs = 0.f;
#pragma unroll
            for (int j = 0; j < 8; j++) {
                sv[j] = __expf(sv[j] - mnew);
                rs += sv[j];
            }
#pragma unroll
            for (int off = 1; off < 16; off <<= 1)
                rs += __shfl_xor_sync(0xFFFFFFFFu, rs, off);
            lrow[i] = lrow[i] * corr + rs;
            const unsigned long long cd = dup2(corr);
            o2[i][0] = mul2(o2[i][0], cd);
            o2[i][1] = mul2(o2[i][1], cd);
#pragma unroll
            for (int j = 0; j < 8; j++) {
                const int kq = tx * 8 + j;
                KP[kq * 132 + p_col(kq, ty * 8 + i)] = sv[j];
            }
        }
        __syncthreads();

        // O += P V  (128x64), thread owns q = ty*8..+7, d = tx*4..+3
#pragma unroll 4
        for (int k = 0; k < 128; k++) {
            const int sh = (k >> 3) << 2;
            const int qo0 = (ty * 8 + sh) & 127;
            const int qo1 = (ty * 8 + 4 + sh) & 127;
            const float4 pf0 = *reinterpret_cast<const float4*>(&KP[k * 132 + qo0]);
            const float4 pf1 = *reinterpret_cast<const float4*>(&KP[k * 132 + qo1]);
            const ulonglong2 vv = *reinterpret_cast<const ulonglong2*>(&Vs[k * 68 + tx * 4]);
            const float pa[8] = {pf0.x, pf0.y, pf0.z, pf0.w, pf1.x, pf1.y, pf1.z, pf1.w};
#pragma unroll
            for (int i = 0; i < 8; i++) {
                const unsigned long long pd = dup2(pa[i]);
                ffma2(o2[i][0], pd, vv.x);
                ffma2(o2[i][1], pd, vv.y);
            }
        }
    }

    // Normalize and write context in [B,S,H,HD] (== [B,S,DIM]) layout
#pragma unroll
    for (int i = 0; i < 8; i++) {
        const float inv = 1.0f / lrow[i];
        const float2 a0 = unp2(o2[i][0]);
        const float2 a1 = unp2(o2[i][1]);
        float4 r;
        r.x = a0.x * inv; r.y = a0.y * inv; r.z = a1.x * inv; r.w = a1.y * inv;
        *reinterpret_cast<float4*>(&g_c[base + (long)(q0 + ty * 8 + i) * DIMd + tx * 4]) = r;
    }
}

// ---------------- launch ----------------
extern "C" void kernel_launch(void* const* d_in, const int* in_sizes, int n_in,
                              void* d_out, int out_size) {
    const float* x  = (const float*)d_in[0];
    const float* Wq = (const float*)d_in[1];
    const float* bq = (const float*)d_in[2];
    const float* Wk = (const float*)d_in[3];
    const float* bk = (const float*)d_in[4];
    const float* Wv = (const float*)d_in[5];
    const float* bv = (const float*)d_in[6];
    const float* Wo = (const float*)d_in[7];
    const float* bo = (const float*)d_in[8];
    float* out = (float*)d_out;

    cudaFuncSetAttribute(k_attn, cudaFuncAttributeMaxDynamicSharedMemorySize, ATTN_SMEM_BYTES);

    k_qkv<<<dim3(GN / 128, GM / 128, 3), 256>>>(x, Wq, bq, Wk, bk, Wv, bv);
    k_attn<<<dim3(Ss / 128, Hh, Bb), 256, ATTN_SMEM_BYTES>>>();
    k_out<<<dim3(GN / 128, GM / 128, 1), 256>>>(Wo, bo, out);
}